// round 2
// baseline (speedup 1.0000x reference)
#include <cuda_runtime.h>
#include <cstdint>
#include <cstddef>

// AlarmworkRNN: scan over 256 steps; only state row 2047 affects the output,
// so the whole problem reduces to a 256-step recurrence on two 1024-vectors.
// Persistent kernel: 128 CTAs, weights cached in SMEM (column slices per CTA),
// one replay-safe grid barrier per step, double-buffered global state.

#define ND   256   // num_data (steps)
#define SEQ  2048  // max_seq_len
#define NI   256   // num_inputs
#define NH   1024  // num_hidden
#define NO   256   // num_outputs
#define GRID 128
#define TPB  256
#define H_PER 8    // hidden columns (per layer) per CTA: 128*8 = 1024
#define O_PER 2    // output columns per CTA: 128*2 = 256

// Grid barrier state: epoch is monotonic across graph replays (no reset needed),
// count always returns to 0 -> deterministic across replays.
__device__ unsigned g_count = 0;
__device__ unsigned g_epoch = 0;
// Double-buffered recurrent state (row 2047 only).
__device__ float g_z1[2][NH];
__device__ float g_z2[2][NH];

__device__ __forceinline__ void grid_barrier() {
    __syncthreads();
    if (threadIdx.x == 0) {
        __threadfence();
        unsigned e = atomicAdd(&g_epoch, 0u);      // acquire-ish read of current epoch
        unsigned prev = atomicAdd(&g_count, 1u);
        if (prev == GRID - 1) {
            atomicExch(&g_count, 0u);
            __threadfence();
            atomicAdd(&g_epoch, 1u);               // release
        } else {
            volatile unsigned* ep = &g_epoch;
            while (*ep == e) { }
        }
        __threadfence();
    }
    __syncthreads();
}

__device__ __forceinline__ float warp_dot4(const float4* __restrict__ v,
                                           const float4* __restrict__ w,
                                           int n4, int lane) {
    float acc = 0.f;
    #pragma unroll 4
    for (int i = lane; i < n4; i += 32) {
        float4 a = v[i];
        float4 b = w[i];
        acc = fmaf(a.x, b.x, acc);
        acc = fmaf(a.y, b.y, acc);
        acc = fmaf(a.z, b.z, acc);
        acc = fmaf(a.w, b.w, acc);
    }
    return acc;
}

__device__ __forceinline__ float warp_reduce(float acc) {
    #pragma unroll
    for (int off = 16; off; off >>= 1)
        acc += __shfl_xor_sync(0xffffffffu, acc, off);
    return acc;
}

extern __shared__ float smem[];

// SMEM layout (floats):
//   [0     .. 8192 )  ws_rec1  : 8 cols x 1024 (column-major slices)
//   [8192  .. 10240)  ws_in1   : 8 cols x 256
//   [10240 .. 18432)  ws_rec2  : 8 cols x 1024
//   [18432 .. 20480)  ws_in2   : 8 cols x 256
//   [20480 .. 22528)  ws_out   : 2 cols x 1024
//   [22528 .. 23552)  z1s
//   [23552 .. 24576)  z2s
//   [24576 .. 25600)  z12s
//   [25600 .. 25856)  xs
//   [25856 .. 25888)  biases
#define SMEM_FLOATS 25888

__global__ void __launch_bounds__(TPB, 1)
rnn_kernel(const float* __restrict__ x,
           const float* __restrict__ W_in1, const float* __restrict__ b_in1,
           const float* __restrict__ W_rec1,
           const float* __restrict__ W_in2, const float* __restrict__ b_in2,
           const float* __restrict__ W_rec2,
           const float* __restrict__ W_out, const float* __restrict__ b_out,
           float* __restrict__ out) {
    float* ws_rec1 = smem;
    float* ws_in1  = smem + 8192;
    float* ws_rec2 = smem + 10240;
    float* ws_in2  = smem + 18432;
    float* ws_out  = smem + 20480;
    float* z1s     = smem + 22528;
    float* z2s     = smem + 23552;
    float* z12s    = smem + 24576;
    float* xs      = smem + 25600;
    float* b1s     = smem + 25856;   // 8
    float* b2s     = smem + 25864;   // 8
    float* bos     = smem + 25872;   // 2

    const int tid   = threadIdx.x;
    const int cta   = blockIdx.x;
    const int jbase = cta * H_PER;   // hidden column base for this CTA
    const int kbase = cta * O_PER;   // output column base for this CTA
    const int w     = tid >> 5;
    const int lane  = tid & 31;

    // --- Stage weight column slices into SMEM (once per launch) ---
    for (int e = tid; e < H_PER * NH; e += TPB) {
        int jj = e >> 10, i = e & (NH - 1);
        ws_rec1[e] = W_rec1[i * NH + jbase + jj];
        ws_rec2[e] = W_rec2[i * NH + jbase + jj];
    }
    for (int e = tid; e < H_PER * NI; e += TPB) {
        int jj = e >> 8, i = e & (NI - 1);
        ws_in1[e] = W_in1[i * NH + jbase + jj];
        ws_in2[e] = W_in2[i * NH + jbase + jj];
    }
    for (int e = tid; e < O_PER * NH; e += TPB) {
        int kk = e >> 10, i = e & (NH - 1);
        ws_out[e] = W_out[i * NO + kbase + kk];
    }
    if (tid < H_PER) {
        b1s[tid] = b_in1[jbase + tid];
        b2s[tid] = b_in2[jbase + tid];
        // Zero-init state buffer 0 (must be re-zeroed on every launch/replay).
        g_z1[0][jbase + tid] = 0.f;
        g_z2[0][jbase + tid] = 0.f;
    }
    if (tid < O_PER) bos[tid] = b_out[kbase + tid];

    // --- Main recurrence: 256 steps + 1 epilogue iteration for out[255] ---
    for (int t = 0; t <= ND; t++) {
        const int p = t & 1;
        grid_barrier();   // state buffer p is now complete & visible

        // Load state vectors for this step into SMEM.
        for (int i = tid; i < NH; i += TPB) {
            float a = g_z1[p][i];
            float b = g_z2[p][i];
            z1s[i]  = a;
            z2s[i]  = b;
            z12s[i] = a + b;
        }
        if (t < ND)
            xs[tid] = x[((size_t)t * SEQ + (SEQ - 1)) * NI + tid];
        __syncthreads();

        // out[t-1] = tanh(z1_state . W_out[:,k] + b_out[k])   (warps 0..1)
        if (t >= 1 && w < O_PER) {
            float acc = warp_dot4((const float4*)z1s,
                                  (const float4*)(ws_out + w * NH), NH / 4, lane);
            acc = warp_reduce(acc);
            if (lane == 0)
                out[(size_t)(t - 1) * NO + kbase + w] = tanhf(acc + bos[w]);
        }

        if (t < ND) {
            // h1: every warp owns one column
            float acc = warp_dot4((const float4*)xs,
                                  (const float4*)(ws_in1 + w * NI), NI / 4, lane)
                      + warp_dot4((const float4*)z12s,
                                  (const float4*)(ws_rec1 + w * NH), NH / 4, lane);
            acc = warp_reduce(acc);
            if (lane == 0)
                g_z1[1 - p][jbase + w] = tanhf(acc + b1s[w]);

            if ((t & 1) == 0) {
                // even step: layer-2 update
                float a2 = warp_dot4((const float4*)xs,
                                     (const float4*)(ws_in2 + w * NI), NI / 4, lane)
                         + warp_dot4((const float4*)z2s,
                                     (const float4*)(ws_rec2 + w * NH), NH / 4, lane);
                a2 = warp_reduce(a2);
                if (lane == 0)
                    g_z2[1 - p][jbase + w] = tanhf(a2 + b2s[w]);
            } else {
                // odd step: layer-2 holds previous state
                if (lane == 0)
                    g_z2[1 - p][jbase + w] = z2s[jbase + w];
            }
        }
    }
}

extern "C" void kernel_launch(void* const* d_in, const int* in_sizes, int n_in,
                              void* d_out, int out_size) {
    const float* x      = (const float*)d_in[0];
    const float* W_in1  = (const float*)d_in[1];
    const float* b_in1  = (const float*)d_in[2];
    const float* W_rec1 = (const float*)d_in[3];
    const float* W_in2  = (const float*)d_in[4];
    const float* b_in2  = (const float*)d_in[5];
    const float* W_rec2 = (const float*)d_in[6];
    const float* W_out  = (const float*)d_in[7];
    const float* b_out  = (const float*)d_in[8];
    float* out = (float*)d_out;

    const size_t shmem = SMEM_FLOATS * sizeof(float);
    cudaFuncSetAttribute(rnn_kernel, cudaFuncAttributeMaxDynamicSharedMemorySize,
                         (int)shmem);
    rnn_kernel<<<GRID, TPB, shmem>>>(x, W_in1, b_in1, W_rec1,
                                     W_in2, b_in2, W_rec2, W_out, b_out, out);
}

// round 5
// speedup vs baseline: 1.4467x; 1.4467x over previous
#include <cuda_runtime.h>
#include <cstdint>
#include <cstddef>

// AlarmworkRNN reduced form: only state row SEQ-1 (2047) reaches the output,
// so the scan collapses to a 256-step recurrence on two 1024-vectors.
//
// R5 = R2's PROVEN kernel (atomic central grid barrier, plain global ld/st for
// state, SMEM weights with identical staging) with latency fixes that do not
// touch the sync protocol:
//   1. barrier split into arrive/wait; out[t-2] matvec + nothing else runs in
//      the spin window (warps 6-7), off the critical path.
//   2. x row prefetched one iteration early (DRAM latency hidden by barrier).
//   3. z2 column kept in a warp-uniform register (no odd-step z2 reload);
//      float4 state loads.

#define ND   256
#define SEQ  2048
#define NI   256
#define NH   1024
#define NO   256
#define GRID 128
#define TPB  256
#define H_PER 8
#define O_PER 2

// R2-proven barrier state: epoch monotonic across replays, count returns to 0.
__device__ unsigned g_count = 0;
__device__ unsigned g_epoch = 0;
// Publication k lives in buffer k&1.
__device__ float g_z1 [2][NH];
__device__ float g_z2 [2][NH];
__device__ float g_z12[2][NH];

__device__ __forceinline__ float warp_dot4(const float4* __restrict__ v,
                                           const float4* __restrict__ wgt,
                                           int n4, int lane) {
    float acc = 0.f;
    #pragma unroll 4
    for (int i = lane; i < n4; i += 32) {
        float4 a = v[i];
        float4 b = wgt[i];
        acc = fmaf(a.x, b.x, acc);
        acc = fmaf(a.y, b.y, acc);
        acc = fmaf(a.z, b.z, acc);
        acc = fmaf(a.w, b.w, acc);
    }
    return acc;
}
__device__ __forceinline__ float warp_reduce(float a) {
    #pragma unroll
    for (int off = 16; off; off >>= 1)
        a += __shfl_xor_sync(0xffffffffu, a, off);
    return a;
}

extern __shared__ float smem[];
// floats: ws_rec1[8192] ws_in1[2048] ws_rec2[8192] ws_in2[2048] ws_out[2048]
//         z12s[1024] z2s[1024] zout[1024] xs[256] b1s[8] b2s[8] bos[2]
#define OFF_REC1 0
#define OFF_IN1  8192
#define OFF_REC2 10240
#define OFF_IN2  18432
#define OFF_OUT  20480
#define OFF_Z12  22528
#define OFF_Z2   23552
#define OFF_ZO   24576
#define OFF_XS   25600
#define OFF_B1   25856
#define OFF_B2   25864
#define OFF_BO   25872
#define SMEM_FLOATS 25888

__global__ void __launch_bounds__(TPB, 1)
rnn_kernel(const float* __restrict__ x,
           const float* __restrict__ W_in1, const float* __restrict__ b_in1,
           const float* __restrict__ W_rec1,
           const float* __restrict__ W_in2, const float* __restrict__ b_in2,
           const float* __restrict__ W_rec2,
           const float* __restrict__ W_out, const float* __restrict__ b_out,
           float* __restrict__ out) {
    float* ws_rec1 = smem + OFF_REC1;
    float* ws_in1  = smem + OFF_IN1;
    float* ws_rec2 = smem + OFF_REC2;
    float* ws_in2  = smem + OFF_IN2;
    float* ws_out  = smem + OFF_OUT;
    float* z12s    = smem + OFF_Z12;
    float* z2s     = smem + OFF_Z2;
    float* zout    = smem + OFF_ZO;
    float* xs      = smem + OFF_XS;
    float* b1s     = smem + OFF_B1;
    float* b2s     = smem + OFF_B2;
    float* bos     = smem + OFF_BO;

    const int tid   = threadIdx.x;
    const int cta   = blockIdx.x;
    const int w     = tid >> 5;
    const int lane  = tid & 31;
    const int jbase = cta * H_PER;
    const int kbase = cta * O_PER;

    // ---- Stage weight column slices into SMEM (R2-verbatim indexing) ----
    for (int e = tid; e < H_PER * NH; e += TPB) {
        int jj = e >> 10, i = e & (NH - 1);
        ws_rec1[e] = W_rec1[i * NH + jbase + jj];
        ws_rec2[e] = W_rec2[i * NH + jbase + jj];
    }
    for (int e = tid; e < H_PER * NI; e += TPB) {
        int jj = e >> 8, i = e & (NI - 1);
        ws_in1[e] = W_in1[i * NH + jbase + jj];
        ws_in2[e] = W_in2[i * NH + jbase + jj];
    }
    for (int e = tid; e < O_PER * NH; e += TPB) {
        int kk = e >> 10, i = e & (NH - 1);
        ws_out[e] = W_out[i * NO + kbase + kk];
    }
    if (tid < H_PER) {
        b1s[tid] = b_in1[jbase + tid];
        b2s[tid] = b_in2[jbase + tid];
    }
    if (tid < O_PER) bos[tid] = b_out[kbase + tid];

    float z2reg = 0.f;   // warp-uniform: z2 value of column jbase+w

    // ---- Iteration 0: compute pub 1 from zero state (no barrier needed) ----
    for (int i = tid; i < NH; i += TPB) { z12s[i] = 0.f; z2s[i] = 0.f; }
    xs[tid] = x[(size_t)(SEQ - 1) * NI + tid];          // x row 0
    __syncthreads();
    {
        float a1 = warp_dot4((const float4*)xs,
                             (const float4*)(ws_in1 + w * NI), NI / 4, lane)
                 + warp_dot4((const float4*)z12s,
                             (const float4*)(ws_rec1 + w * NH), NH / 4, lane);
        a1 = warp_reduce(a1);
        float a2 = warp_dot4((const float4*)xs,
                             (const float4*)(ws_in2 + w * NI), NI / 4, lane)
                 + warp_dot4((const float4*)z2s,
                             (const float4*)(ws_rec2 + w * NH), NH / 4, lane);
        a2 = warp_reduce(a2);
        const float z1n = tanhf(a1 + b1s[w]);
        z2reg = tanhf(a2 + b2s[w]);
        if (lane == 0) {            // publish pub 1 (buffer 1), R2-style plain st
            g_z1 [1][jbase + w] = z1n;
            g_z2 [1][jbase + w] = z2reg;
            g_z12[1][jbase + w] = z1n + z2reg;
        }
    }

    float xpref = __ldg(&x[((size_t)1 * SEQ + (SEQ - 1)) * NI + tid]);  // row 1

    // ---- Iterations 1..ND: barrier(pub t) -> load pub t -> compute pub t+1 ----
    for (int t = 1; t <= ND; t++) {
        const int cb   = t & 1;
        const int nbuf = (t + 1) & 1;
        const bool ev  = ((t & 1) == 0);

        // Arrive (R2 grid_barrier, split; window work on idle warps).
        __syncthreads();
        if (tid == 0) {
            __threadfence();
            unsigned e = atomicAdd(&g_epoch, 0u);
            unsigned prev = atomicAdd(&g_count, 1u);
            if (prev == GRID - 1) {
                atomicExch(&g_count, 0u);
                __threadfence();
                atomicAdd(&g_epoch, 1u);
            } else {
                volatile unsigned* ep = &g_epoch;
                while (*ep == e) { }
            }
            __threadfence();
        } else if (w >= 6 && t >= 2) {
            // out[t-2] = tanh(z1(pub t-1) . Wout + bo) from stashed zout.
            float a = warp_dot4((const float4*)zout,
                                (const float4*)(ws_out + (w - 6) * NH),
                                NH / 4, lane);
            a = warp_reduce(a);
            if (lane == 0)
                out[(size_t)(t - 2) * NO + kbase + (w - 6)] =
                    tanhf(a + bos[w - 6]);
        }
        __syncthreads();   // wait: pub t visible grid-wide

        // Load pub t (plain loads, R2 caching behavior; float4 vectorized).
        ((float4*)z12s)[tid] = ((const float4*)g_z12[cb])[tid];
        ((float4*)zout)[tid] = ((const float4*)g_z1 [cb])[tid];
        if (ev)
            ((float4*)z2s)[tid] = ((const float4*)g_z2[cb])[tid];
        xs[tid] = xpref;
        __syncthreads();

        if (t < ND) {
            // Prefetch x row t+1 (consumed next iteration; hidden by barrier).
            if (t + 1 < ND)
                xpref = __ldg(&x[((size_t)(t + 1) * SEQ + (SEQ - 1)) * NI + tid]);

            float a1 = warp_dot4((const float4*)xs,
                                 (const float4*)(ws_in1 + w * NI), NI / 4, lane)
                     + warp_dot4((const float4*)z12s,
                                 (const float4*)(ws_rec1 + w * NH), NH / 4, lane);
            a1 = warp_reduce(a1);
            float a2 = 0.f;
            if (ev) {
                a2 = warp_dot4((const float4*)xs,
                               (const float4*)(ws_in2 + w * NI), NI / 4, lane)
                   + warp_dot4((const float4*)z2s,
                               (const float4*)(ws_rec2 + w * NH), NH / 4, lane);
                a2 = warp_reduce(a2);
            }
            const float z1n = tanhf(a1 + b1s[w]);
            if (ev) z2reg = tanhf(a2 + b2s[w]);
            if (lane == 0) {       // publish pub t+1 (plain stores, R2-style)
                g_z1 [nbuf][jbase + w] = z1n;
                g_z2 [nbuf][jbase + w] = z2reg;   // odd t: republish held z2
                g_z12[nbuf][jbase + w] = z1n + z2reg;
            }
        }
    }

    // ---- Tail: out[ND-1] from pub ND (zout stashed at iter ND) ----
    if (w >= 6) {
        float a = warp_dot4((const float4*)zout,
                            (const float4*)(ws_out + (w - 6) * NH), NH / 4, lane);
        a = warp_reduce(a);
        if (lane == 0)
            out[(size_t)(ND - 1) * NO + kbase + (w - 6)] = tanhf(a + bos[w - 6]);
    }
}

extern "C" void kernel_launch(void* const* d_in, const int* in_sizes, int n_in,
                              void* d_out, int out_size) {
    const float* x      = (const float*)d_in[0];
    const float* W_in1  = (const float*)d_in[1];
    const float* b_in1  = (const float*)d_in[2];
    const float* W_rec1 = (const float*)d_in[3];
    const float* W_in2  = (const float*)d_in[4];
    const float* b_in2  = (const float*)d_in[5];
    const float* W_rec2 = (const float*)d_in[6];
    const float* W_out  = (const float*)d_in[7];
    const float* b_out  = (const float*)d_in[8];
    float* out = (float*)d_out;

    const size_t shmem = SMEM_FLOATS * sizeof(float);
    cudaFuncSetAttribute(rnn_kernel, cudaFuncAttributeMaxDynamicSharedMemorySize,
                         (int)shmem);
    rnn_kernel<<<GRID, TPB, shmem>>>(x, W_in1, b_in1, W_rec1,
                                     W_in2, b_in2, W_rec2, W_out, b_out, out);
}